// round 13
// baseline (speedup 1.0000x reference)
#include <cuda_runtime.h>
#include <cuda_bf16.h>
#include <mma.h>
#include <math.h>
#include <stdint.h>

using namespace nvcuda;

#define NFEAT 128
#define HID   64
#define NCLS  40
#define MAXN  100000
#define MAXE  600000
#define SCAN_CHUNK 4096
#define PADW 136                      // gemm1 smem row pad (bf16 elems)
#define PADA2 72                      // gemm2 A row pad (K=64)
#define PADB2 88                      // gemm2 B row pad (N=80)

// ---------------- scratch (padded for unguarded frag stores) -----
__device__ float g_t1[(size_t)(MAXN + 256) * 128];
__device__ float g_t2[(size_t)(MAXN + 128) * 80];
__device__ __nv_bfloat16 g_hhi[(size_t)MAXN * 64];
__device__ __nv_bfloat16 g_hlo[(size_t)MAXN * 64];
__device__ __nv_bfloat16 g_w1hi[128 * 128];
__device__ __nv_bfloat16 g_w1lo[128 * 128];
__device__ __nv_bfloat16 g_w2hi[64 * 80];
__device__ __nv_bfloat16 g_w2lo[64 * 80];
__device__ int   g_deg[MAXN];
__device__ int   g_cur[MAXN];
__device__ int   g_rowptr[MAXN + 1];
__device__ int   g_adj[MAXE];
__device__ int   g_bsum[32];
__device__ int   g_bflag[32];

// ---------------- side stream + events (created once at load) -------
static cudaStream_t g_s2;
static cudaEvent_t  g_evFork, g_evG1;
static struct _StreamInit {
    _StreamInit() {
        cudaStreamCreateWithFlags(&g_s2, cudaStreamNonBlocking);
        cudaEventCreateWithFlags(&g_evFork, cudaEventDisableTiming);
        cudaEventCreateWithFlags(&g_evG1,   cudaEventDisableTiming);
    }
} g_streamInit;

// ---------------- bf16 split helper ----------------
__device__ __forceinline__ void split4(const float4& v, uint32_t* hi2, uint32_t* lo2) {
    uint32_t h01, h23;
    asm("cvt.rn.bf16x2.f32 %0, %1, %2;" : "=r"(h01) : "f"(v.y), "f"(v.x));
    asm("cvt.rn.bf16x2.f32 %0, %1, %2;" : "=r"(h23) : "f"(v.w), "f"(v.z));
    float l0 = v.x - __uint_as_float(h01 << 16);
    float l1 = v.y - __uint_as_float(h01 & 0xffff0000u);
    float l2 = v.z - __uint_as_float(h23 << 16);
    float l3 = v.w - __uint_as_float(h23 & 0xffff0000u);
    asm("cvt.rn.bf16x2.f32 %0, %1, %2;" : "=r"(lo2[0]) : "f"(l1), "f"(l0));
    asm("cvt.rn.bf16x2.f32 %0, %1, %2;" : "=r"(lo2[1]) : "f"(l3), "f"(l2));
    hi2[0] = h01; hi2[1] = h23;
}

// ---------------- per-block inline dtype detect ----------------
__device__ __forceinline__ int detect_is64(const void* ei, int E, int N,
                                           int tid, int* s_flag) {
    if (tid < 32) {
        int samples = (E < 32) ? E : 32;
        bool bad = false;
        if (tid < samples) {
            long long v = ((const long long*)ei)[tid];
            bad = (v < 0 || v >= (long long)N);
        }
        unsigned m = __ballot_sync(0xffffffffu, bad);
        if (tid == 0) *s_flag = (m == 0u) ? 1 : 0;
    }
    __syncthreads();
    return *s_flag;
}

__device__ __forceinline__ int load_idx2(const void* ei, int pos, int is64) {
    if (is64) return (int)((const long long*)ei)[pos];
    return ((const int*)ei)[pos];
}

// ---------------- combined W split: W1 -> g_w1*, W2 -> g_w2* ----------
__global__ void k_wsplit_all(const float* __restrict__ W1l, const float* __restrict__ W1r,
                             const float* __restrict__ W2l, const float* __restrict__ W2r) {
    int p = blockIdx.x * blockDim.x + threadIdx.x;
    if (p < 4096) {
        int k = p >> 5, cq = p & 31;
        const float* src = (cq < 16) ? (W1l + k * 64 + cq * 4)
                                     : (W1r + k * 64 + (cq - 16) * 4);
        float4 v = *(const float4*)src;
        uint32_t hi2[2], lo2[2];
        split4(v, hi2, lo2);
        ((uint32_t*)(g_w1hi + k * 128 + cq * 4))[0] = hi2[0];
        ((uint32_t*)(g_w1hi + k * 128 + cq * 4))[1] = hi2[1];
        ((uint32_t*)(g_w1lo + k * 128 + cq * 4))[0] = lo2[0];
        ((uint32_t*)(g_w1lo + k * 128 + cq * 4))[1] = lo2[1];
    } else if (p < 4096 + 1280) {
        int q = p - 4096;
        int k = q / 20, cq = q % 20;
        const float* src = (cq < 10) ? (W2l + k * 40 + cq * 4)
                                     : (W2r + k * 40 + (cq - 10) * 4);
        float4 v = *(const float4*)src;
        uint32_t hi2[2], lo2[2];
        split4(v, hi2, lo2);
        ((uint32_t*)(g_w2hi + k * 80 + cq * 4))[0] = hi2[0];
        ((uint32_t*)(g_w2hi + k * 80 + cq * 4))[1] = hi2[1];
        ((uint32_t*)(g_w2lo + k * 80 + cq * 4))[0] = lo2[0];
        ((uint32_t*)(g_w2lo + k * 80 + cq * 4))[1] = lo2[1];
    }
}

// g_deg is zero here (module load / re-zeroed by k_scan every call)
__global__ void k_hist(const void* __restrict__ ei, int E, int N) {
    __shared__ int s_flag;
    int is64 = detect_is64(ei, E, N, threadIdx.x, &s_flag);
    int half = (E + 1) >> 1;
    int e = blockIdx.x * blockDim.x + threadIdx.x;
    int d0 = -1, d1 = -1;
    if (e < half)        d0 = min(max(load_idx2(ei, E + e, is64), 0), N - 1);
    if (e + half < E)    d1 = min(max(load_idx2(ei, E + e + half, is64), 0), N - 1);
    if (d0 >= 0) atomicAdd(&g_deg[d0], 1);
    if (d1 >= 0) atomicAdd(&g_deg[d1], 1);
}

// ---- single-pass scan with decoupled block-sum lookback ----
__global__ void k_scan(int n) {
    const int tid = threadIdx.x, lane = tid & 31, wid = tid >> 5;
    const int bid = blockIdx.x;
    __shared__ int wsum[32];
    __shared__ int s_off;
    int idx = bid * SCAN_CHUNK + tid * 4;
    int v0 = 0, v1 = 0, v2 = 0, v3 = 0;
    if (idx + 0 < n) { v0 = g_deg[idx + 0]; g_deg[idx + 0] = 0; }
    if (idx + 1 < n) { v1 = g_deg[idx + 1]; g_deg[idx + 1] = 0; }
    if (idx + 2 < n) { v2 = g_deg[idx + 2]; g_deg[idx + 2] = 0; }
    if (idx + 3 < n) { v3 = g_deg[idx + 3]; g_deg[idx + 3] = 0; }
    int s = v0 + v1 + v2 + v3;
    int sc = s;
    #pragma unroll
    for (int d = 1; d < 32; d <<= 1) {
        int t = __shfl_up_sync(0xffffffffu, sc, d);
        if (lane >= d) sc += t;
    }
    if (lane == 31) wsum[wid] = sc;
    __syncthreads();
    if (wid == 0) {
        int ws = wsum[lane];
        #pragma unroll
        for (int d = 1; d < 32; d <<= 1) {
            int t = __shfl_up_sync(0xffffffffu, ws, d);
            if (lane >= d) ws += t;
        }
        wsum[lane] = ws;
    }
    __syncthreads();
    int warp_excl = (wid == 0) ? 0 : wsum[wid - 1];
    int excl = warp_excl + (sc - s);

    if (tid == 1023) {
        g_bsum[bid] = warp_excl + sc;
        __threadfence();
        atomicExch(&g_bflag[bid], 1);
    }
    if (tid < 32) {
        int acc = 0;
        for (int j = lane; j < bid; j += 32) {
            while (atomicAdd(&g_bflag[j], 0) == 0) {}
            acc += atomicAdd(&g_bsum[j], 0);
        }
        #pragma unroll
        for (int d = 16; d > 0; d >>= 1)
            acc += __shfl_down_sync(0xffffffffu, acc, d);
        if (lane == 0) s_off = acc;
    }
    __syncthreads();
    int off = s_off + excl;
    int p0 = off + v0, p1 = p0 + v1, p2 = p1 + v2, p3 = p2 + v3;
    if (idx + 0 < n) g_rowptr[idx + 1] = p0;
    if (idx + 1 < n) g_rowptr[idx + 2] = p1;
    if (idx + 2 < n) g_rowptr[idx + 3] = p2;
    if (idx + 3 < n) g_rowptr[idx + 4] = p3;
    if (bid == 0 && tid == 0) g_rowptr[0] = 0;
}

// g_cur is zero here (module load / reset by final k_finish2)
__global__ void k_fill(const void* __restrict__ ei, int E, int N) {
    __shared__ int s_flag;
    int is64 = detect_is64(ei, E, N, threadIdx.x, &s_flag);
    if (blockIdx.x == 0 && threadIdx.x < 32) g_bflag[threadIdx.x] = 0;
    int half = (E + 1) >> 1;
    int e = blockIdx.x * blockDim.x + threadIdx.x;
    if (e < half) {
        int dst = min(max(load_idx2(ei, E + e, is64), 0), N - 1);
        int src = min(max(load_idx2(ei, e, is64), 0), N - 1);
        int pos = g_rowptr[dst] + atomicAdd(&g_cur[dst], 1);
        if (pos < E) g_adj[pos] = src;
    }
    if (e + half < E) {
        int dst = min(max(load_idx2(ei, E + e + half, is64), 0), N - 1);
        int src = min(max(load_idx2(ei, e + half, is64), 0), N - 1);
        int pos = g_rowptr[dst] + atomicAdd(&g_cur[dst], 1);
        if (pos < E) g_adj[pos] = src;
    }
}

// ------------- GEMM1 v3, persistent: T1 = X @ [W1l|W1r] (bf16 3-pass split) ---
// 256x128 tile, 512 threads (16 warps = 4m x 4n, warp tile 64x32).
// W hi/lo resident in smem (once per SM); 209KB smem -> 1 CTA/SM.
// Per k-step: 12 LDSM : 24 MMA.  Direct unguarded stores (g_t1 padded +256).
#define GEMM1_SMEM ((2 * 128 + 2 * 256) * PADW * 2)

__global__ void __launch_bounds__(512, 1)
k_gemm1_wmma(const float* __restrict__ X, float* __restrict__ T, int n) {
    extern __shared__ char smraw[];
    __nv_bfloat16* Whi = (__nv_bfloat16*)smraw;          // [128][PADW]
    __nv_bfloat16* Wlo = Whi + 128 * PADW;
    __nv_bfloat16* Ahi = Wlo + 128 * PADW;               // [256][PADW]
    __nv_bfloat16* Alo = Ahi + 256 * PADW;
    const int tid = threadIdx.x, wid = tid >> 5;

    // W resident: load once per CTA (2048 uint4 per matrix)
    #pragma unroll
    for (int it = 0; it < 4; it++) {
        int p = it * 512 + tid;
        int k = p >> 4, c = p & 15;
        *(uint4*)(Whi + k * PADW + c * 8) = ((const uint4*)g_w1hi)[p];
        *(uint4*)(Wlo + k * PADW + c * 8) = ((const uint4*)g_w1lo)[p];
    }

    const int m0 = (wid & 3) * 64;          // 4 m-positions of 64 rows
    const int n0 = (wid >> 2) * 32;         // 4 n-positions of 32 cols
    const int ntiles = (n + 255) >> 8;

    for (int t = blockIdx.x; t < ntiles; t += gridDim.x) {
        const int row0 = t << 8;
        __syncthreads();               // prev tile readers done (also orders W 1st iter)
        // convert X tile (256 rows x 128 cols): 8192 float4 slots
        #pragma unroll 4
        for (int it = 0; it < 16; it++) {
            int p = it * 512 + tid;
            int r = p >> 5, cq = p & 31;
            float4 v = make_float4(0.f, 0.f, 0.f, 0.f);
            if (row0 + r < n) v = ((const float4*)(X + (size_t)(row0 + r) * 128))[cq];
            uint32_t hi2[2], lo2[2];
            split4(v, hi2, lo2);
            uint32_t* ah = (uint32_t*)(Ahi + r * PADW + cq * 4);
            uint32_t* al = (uint32_t*)(Alo + r * PADW + cq * 4);
            ah[0] = hi2[0]; ah[1] = hi2[1];
            al[0] = lo2[0]; al[1] = lo2[1];
        }
        __syncthreads();

        wmma::fragment<wmma::accumulator, 16, 16, 16, float> acc[4][2];
        #pragma unroll
        for (int r = 0; r < 4; r++)
            #pragma unroll
            for (int c = 0; c < 2; c++) wmma::fill_fragment(acc[r][c], 0.f);

        #pragma unroll
        for (int k = 0; k < 128; k += 16) {
            // stage 1: Ahi x Whi
            wmma::fragment<wmma::matrix_a, 16, 16, 16, __nv_bfloat16, wmma::row_major> ah[4];
            wmma::fragment<wmma::matrix_b, 16, 16, 16, __nv_bfloat16, wmma::row_major> bh[2];
            #pragma unroll
            for (int r = 0; r < 4; r++)
                wmma::load_matrix_sync(ah[r], Ahi + (m0 + r * 16) * PADW + k, PADW);
            wmma::load_matrix_sync(bh[0], Whi + k * PADW + n0,      PADW);
            wmma::load_matrix_sync(bh[1], Whi + k * PADW + n0 + 16, PADW);
            #pragma unroll
            for (int r = 0; r < 4; r++) {
                wmma::mma_sync(acc[r][0], ah[r], bh[0], acc[r][0]);
                wmma::mma_sync(acc[r][1], ah[r], bh[1], acc[r][1]);
            }
            // stage 2: Ahi x Wlo
            {
                wmma::fragment<wmma::matrix_b, 16, 16, 16, __nv_bfloat16, wmma::row_major> bl[2];
                wmma::load_matrix_sync(bl[0], Wlo + k * PADW + n0,      PADW);
                wmma::load_matrix_sync(bl[1], Wlo + k * PADW + n0 + 16, PADW);
                #pragma unroll
                for (int r = 0; r < 4; r++) {
                    wmma::mma_sync(acc[r][0], ah[r], bl[0], acc[r][0]);
                    wmma::mma_sync(acc[r][1], ah[r], bl[1], acc[r][1]);
                }
            }
            // stage 3: Alo x Whi (reuses bh; ah regs recycled into al)
            #pragma unroll
            for (int r = 0; r < 4; r++) {
                wmma::fragment<wmma::matrix_a, 16, 16, 16, __nv_bfloat16, wmma::row_major> al;
                wmma::load_matrix_sync(al, Alo + (m0 + r * 16) * PADW + k, PADW);
                wmma::mma_sync(acc[r][0], al, bh[0], acc[r][0]);
                wmma::mma_sync(acc[r][1], al, bh[1], acc[r][1]);
            }
        }

        // direct global stores (g_t1 padded by 256 rows)
        #pragma unroll
        for (int r = 0; r < 4; r++)
            #pragma unroll
            for (int c = 0; c < 2; c++)
                wmma::store_matrix_sync(T + (size_t)(row0 + m0 + r * 16) * 128 + n0 + c * 16,
                                        acc[r][c], 128, wmma::mem_row_major);
    }
}

// -------- finish layer1: gather t1 + mean + bias + sigmoid -> h (bf16 hi/lo) ----
__global__ void k_finish1(const float* __restrict__ T, const float* __restrict__ bias,
                          int n) {
    int gid = blockIdx.x * blockDim.x + threadIdx.x;     // node*16 + q
    int node = gid >> 4;
    int q = gid & 15;
    if (node >= n) return;
    int s = g_rowptr[node], e = g_rowptr[node + 1];
    float4 a0 = make_float4(0.f, 0.f, 0.f, 0.f);
    float4 a1 = make_float4(0.f, 0.f, 0.f, 0.f);
    int p = s;
    for (; p + 1 < e; p += 2) {
        int j0 = g_adj[p], j1 = g_adj[p + 1];
        float4 v0 = *(const float4*)(T + (size_t)j0 * 128 + q * 4);
        float4 v1 = *(const float4*)(T + (size_t)j1 * 128 + q * 4);
        a0.x += v0.x; a0.y += v0.y; a0.z += v0.z; a0.w += v0.w;
        a1.x += v1.x; a1.y += v1.y; a1.z += v1.z; a1.w += v1.w;
    }
    if (p < e) {
        int j = g_adj[p];
        float4 v = *(const float4*)(T + (size_t)j * 128 + q * 4);
        a0.x += v.x; a0.y += v.y; a0.z += v.z; a0.w += v.w;
    }
    a0.x += a1.x; a0.y += a1.y; a0.z += a1.z; a0.w += a1.w;
    float inv = 1.f / fmaxf((float)(e - s), 1.f);
    float4 r = *(const float4*)(T + (size_t)node * 128 + 64 + q * 4);
    float4 b = *(const float4*)(bias + q * 4);
    float4 o;
    o.x = fmaf(a0.x, inv, r.x + b.x);
    o.y = fmaf(a0.y, inv, r.y + b.y);
    o.z = fmaf(a0.z, inv, r.z + b.z);
    o.w = fmaf(a0.w, inv, r.w + b.w);
    o.x = 1.f / (1.f + expf(-o.x));
    o.y = 1.f / (1.f + expf(-o.y));
    o.z = 1.f / (1.f + expf(-o.z));
    o.w = 1.f / (1.f + expf(-o.w));
    uint32_t hi2[2], lo2[2];
    split4(o, hi2, lo2);
    *(uint2*)(g_hhi + (size_t)node * 64 + q * 4) = make_uint2(hi2[0], hi2[1]);
    *(uint2*)(g_hlo + (size_t)node * 64 + q * 4) = make_uint2(lo2[0], lo2[1]);
}

// ------------- GEMM2, persistent: T2 = H @ [W2l|W2r] (pre-split H) ------------
#define GEMM2_SMEM ((2 * 64 * PADB2 + 2 * 128 * PADA2) * 2)

__global__ void __launch_bounds__(320, 2)
k_gemm2_wmma(float* __restrict__ T, int n) {
    extern __shared__ char smraw[];
    __nv_bfloat16* Whi = (__nv_bfloat16*)smraw;           // [64][PADB2]
    __nv_bfloat16* Wlo = Whi + 64 * PADB2;
    __nv_bfloat16* Ahi = Wlo + 64 * PADB2;                // [128][PADA2]
    __nv_bfloat16* Alo = Ahi + 128 * PADA2;
    const int tid = threadIdx.x, wid = tid >> 5;

    for (int p = tid; p < 640; p += 320) {
        int k = p / 10, c = p % 10;
        *(uint4*)(Whi + k * PADB2 + c * 8) = ((const uint4*)g_w2hi)[p];
        *(uint4*)(Wlo + k * PADB2 + c * 8) = ((const uint4*)g_w2lo)[p];
    }

    const int n0 = (wid % 5) * 16;
    const int m0 = (wid / 5) * 64;
    const int ntiles = (n + 127) >> 7;

    for (int t = blockIdx.x; t < ntiles; t += gridDim.x) {
        const int row0 = t << 7;
        __syncthreads();
        for (int p = tid; p < 2048; p += 320) {
            int r = p >> 4, cq = p & 15;
            uint2 hv = make_uint2(0u, 0u), lv = make_uint2(0u, 0u);
            if (row0 + r < n) {
                hv = *(const uint2*)(g_hhi + (size_t)(row0 + r) * 64 + cq * 4);
                lv = *(const uint2*)(g_hlo + (size_t)(row0 + r) * 64 + cq * 4);
            }
            *(uint2*)(Ahi + r * PADA2 + cq * 4) = hv;
            *(uint2*)(Alo + r * PADA2 + cq * 4) = lv;
        }
        __syncthreads();

        wmma::fragment<wmma::accumulator, 16, 16, 16, float> acc[4];
        #pragma unroll
        for (int r = 0; r < 4; r++) wmma::fill_fragment(acc[r], 0.f);

        #pragma unroll
        for (int k = 0; k < 64; k += 16) {
            wmma::fragment<wmma::matrix_b, 16, 16, 16, __nv_bfloat16, wmma::row_major> bh, bl;
            wmma::load_matrix_sync(bh, Whi + k * PADB2 + n0, PADB2);
            wmma::load_matrix_sync(bl, Wlo + k * PADB2 + n0, PADB2);
            #pragma unroll
            for (int r = 0; r < 4; r++) {
                wmma::fragment<wmma::matrix_a, 16, 16, 16, __nv_bfloat16, wmma::row_major> ah, al;
                wmma::load_matrix_sync(ah, Ahi + (m0 + r * 16) * PADA2 + k, PADA2);
                wmma::load_matrix_sync(al, Alo + (m0 + r * 16) * PADA2 + k, PADA2);
                wmma::mma_sync(acc[r], ah, bh, acc[r]);
                wmma::mma_sync(acc[r], ah, bl, acc[r]);
                wmma::mma_sync(acc[r], al, bh, acc[r]);
            }
        }

        #pragma unroll
        for (int r = 0; r < 4; r++)
            wmma::store_matrix_sync(T + (size_t)(row0 + m0 + r * 16) * 80 + n0,
                                    acc[r], 80, wmma::mem_row_major);
    }
}

// -------- final: aggregate t2 + mean + residual + bias --------
__global__ void k_finish2(const float* __restrict__ T, const float* __restrict__ bias,
                          float* __restrict__ out, int n) {
    constexpr int Q = 10;
    int gid = blockIdx.x * blockDim.x + threadIdx.x;
    int node = gid / Q;
    int q = gid - node * Q;
    if (node >= n) return;
    int s = g_rowptr[node], e = g_rowptr[node + 1];
    float4 a0 = make_float4(0.f, 0.f, 0.f, 0.f);
    float4 a1 = make_float4(0.f, 0.f, 0.f, 0.f);
    int p = s;
    for (; p + 1 < e; p += 2) {
        int j0 = g_adj[p], j1 = g_adj[p + 1];
        float4 v0 = *(const float4*)(T + (size_t)j0 * 80 + q * 4);
        float4 v1 = *(const float4*)(T + (size_t)j1 * 80 + q * 4);
        a0.x += v0.x; a0.y += v0.y; a0.z += v0.z; a0.w += v0.w;
        a1.x += v1.x; a1.y += v1.y; a1.z += v1.z; a1.w += v1.w;
    }
    if (p < e) {
        int j = g_adj[p];
        float4 v = *(const float4*)(T + (size_t)j * 80 + q * 4);
        a0.x += v.x; a0.y += v.y; a0.z += v.z; a0.w += v.w;
    }
    a0.x += a1.x; a0.y += a1.y; a0.z += a1.z; a0.w += a1.w;
    float inv = 1.f / fmaxf((float)(e - s), 1.f);
    float4 r = *(const float4*)(T + (size_t)node * 80 + 40 + q * 4);
    float4 b = *(const float4*)(bias + q * 4);
    float4 o;
    o.x = fmaf(a0.x, inv, r.x + b.x);
    o.y = fmaf(a0.y, inv, r.y + b.y);
    o.z = fmaf(a0.z, inv, r.z + b.z);
    o.w = fmaf(a0.w, inv, r.w + b.w);
    *(float4*)(out + (size_t)node * 40 + q * 4) = o;
    if (q == 0) g_cur[node] = 0;   // reset for next call
}

// ---------------- launch ----------------
extern "C" void kernel_launch(void* const* d_in, const int* in_sizes, int n_in,
                              void* d_out, int out_size) {
    const float* x   = (const float*)d_in[0];
    const void*  ei  = d_in[1];
    const float* W1l = (const float*)d_in[2];
    const float* b1  = (const float*)d_in[3];
    const float* W1r = (const float*)d_in[4];
    const float* W2l = (const float*)d_in[5];
    const float* b2  = (const float*)d_in[6];
    const float* W2r = (const float*)d_in[7];
    float* out = (float*)d_out;

    const int N = in_sizes[0] / NFEAT;
    const int E = in_sizes[1] / 2;
    const int NB = (N + SCAN_CHUNK - 1) / SCAN_CHUNK;
    const int EH = ((E + 1) / 2 + 255) / 256;

    void *t1p, *t2p;
    cudaGetSymbolAddress(&t1p, g_t1);
    cudaGetSymbolAddress(&t2p, g_t2);

    cudaFuncSetAttribute(k_gemm1_wmma, cudaFuncAttributeMaxDynamicSharedMemorySize, GEMM1_SMEM);
    cudaFuncSetAttribute(k_gemm2_wmma, cudaFuncAttributeMaxDynamicSharedMemorySize, GEMM2_SMEM);

    int g1 = 148;                          // 1 CTA/SM persistent (209KB smem)
    int nt1 = (N + 255) / 256;
    if (g1 > nt1) g1 = nt1;
    int g2 = 296;
    if (g2 > (N + 127) / 128) g2 = (N + 127) / 128;

    // fork: side stream = weights + GEMM1; main stream = graph build
    cudaEventRecord(g_evFork, 0);
    cudaStreamWaitEvent(g_s2, g_evFork, 0);

    k_wsplit_all<<<21, 256, 0, g_s2>>>(W1l, W1r, W2l, W2r);          // #1
    k_hist<<<EH, 256>>>(ei, E, N);                                   // #2
    k_scan<<<NB, 1024>>>(N);                                         // #3
    k_gemm1_wmma<<<g1, 512, GEMM1_SMEM, g_s2>>>(x, (float*)t1p, N);  // #4
    k_fill<<<EH, 256>>>(ei, E, N);                                   // #5

    // join
    cudaEventRecord(g_evG1, g_s2);
    cudaStreamWaitEvent(0, g_evG1, 0);

    // tail
    int tot1 = N * 16;
    k_finish1<<<(tot1 + 255) / 256, 256>>>((const float*)t1p, b1, N);          // #6
    k_gemm2_wmma<<<g2, 320, GEMM2_SMEM>>>((float*)t2p, N);                     // #7
    int tot2 = N * 10;
    k_finish2<<<(tot2 + 255) / 256, 256>>>((const float*)t2p, b2, out, N);     // #8
}

// round 14
// speedup vs baseline: 1.1681x; 1.1681x over previous
#include <cuda_runtime.h>
#include <cuda_fp16.h>
#include <mma.h>
#include <math.h>
#include <stdint.h>

using namespace nvcuda;

#define NFEAT 128
#define HID   64
#define NCLS  40
#define MAXN  100000
#define MAXE  600000
#define SCAN_CHUNK 4096
#define PADW 136                      // gemm1 smem row pad (fp16 elems)
#define PADA2 72                      // gemm2 A row pad (K=64)
#define PADB2 88                      // gemm2 B row pad (N=80)

// ---------------- scratch (padded for unguarded frag stores) -----
__device__ float g_t1[(size_t)(MAXN + 256) * 128];
__device__ float g_t2[(size_t)(MAXN + 128) * 80];
__device__ __half g_hhi[(size_t)MAXN * 64];   // hidden, exact fp16 split (hi)
__device__ __half g_hlo[(size_t)MAXN * 64];   //                          (lo)
__device__ __half g_w1h[128 * 128];           // W1 = [W1l|W1r], fp16 (single)
__device__ __half g_w2h[64 * 80];             // W2 = [W2l|W2r], fp16 (single)
__device__ int   g_deg[MAXN];
__device__ int   g_cur[MAXN];
__device__ int   g_rowptr[MAXN + 1];
__device__ int   g_adj[MAXE];
__device__ int   g_bsum[32];
__device__ int   g_bflag[32];

// ---------------- side stream + events (created once at load) -------
static cudaStream_t g_s2;
static cudaEvent_t  g_evFork, g_evG1;
static struct _StreamInit {
    _StreamInit() {
        cudaStreamCreateWithFlags(&g_s2, cudaStreamNonBlocking);
        cudaEventCreateWithFlags(&g_evFork, cudaEventDisableTiming);
        cudaEventCreateWithFlags(&g_evG1,   cudaEventDisableTiming);
    }
} g_streamInit;

// ---------------- fp16 exact-split helper: v = hi + lo (2x11-bit mantissa) ----
__device__ __forceinline__ void split4h(const float4& v, uint32_t* hi2, uint32_t* lo2) {
    __half2 h01 = __floats2half2_rn(v.x, v.y);
    __half2 h23 = __floats2half2_rn(v.z, v.w);
    float2 f01 = __half22float2(h01);
    float2 f23 = __half22float2(h23);
    __half2 l01 = __floats2half2_rn(v.x - f01.x, v.y - f01.y);
    __half2 l23 = __floats2half2_rn(v.z - f23.x, v.w - f23.y);
    hi2[0] = *reinterpret_cast<uint32_t*>(&h01);
    hi2[1] = *reinterpret_cast<uint32_t*>(&h23);
    lo2[0] = *reinterpret_cast<uint32_t*>(&l01);
    lo2[1] = *reinterpret_cast<uint32_t*>(&l23);
}

// ---------------- per-block inline dtype detect ----------------
__device__ __forceinline__ int detect_is64(const void* ei, int E, int N,
                                           int tid, int* s_flag) {
    if (tid < 32) {
        int samples = (E < 32) ? E : 32;
        bool bad = false;
        if (tid < samples) {
            long long v = ((const long long*)ei)[tid];
            bad = (v < 0 || v >= (long long)N);
        }
        unsigned m = __ballot_sync(0xffffffffu, bad);
        if (tid == 0) *s_flag = (m == 0u) ? 1 : 0;
    }
    __syncthreads();
    return *s_flag;
}

__device__ __forceinline__ int load_idx2(const void* ei, int pos, int is64) {
    if (is64) return (int)((const long long*)ei)[pos];
    return ((const int*)ei)[pos];
}

// ---------------- combined W convert (single fp16): W1, W2 ----------
__global__ void k_wsplit_all(const float* __restrict__ W1l, const float* __restrict__ W1r,
                             const float* __restrict__ W2l, const float* __restrict__ W2r) {
    int p = blockIdx.x * blockDim.x + threadIdx.x;
    if (p < 4096) {                                    // W1: 4096 float4 slots
        int k = p >> 5, cq = p & 31;
        const float* src = (cq < 16) ? (W1l + k * 64 + cq * 4)
                                     : (W1r + k * 64 + (cq - 16) * 4);
        float4 v = *(const float4*)src;
        __half2 h01 = __floats2half2_rn(v.x, v.y);
        __half2 h23 = __floats2half2_rn(v.z, v.w);
        ((uint32_t*)(g_w1h + k * 128 + cq * 4))[0] = *reinterpret_cast<uint32_t*>(&h01);
        ((uint32_t*)(g_w1h + k * 128 + cq * 4))[1] = *reinterpret_cast<uint32_t*>(&h23);
    } else if (p < 4096 + 1280) {                      // W2: 1280 float4 slots
        int q = p - 4096;
        int k = q / 20, cq = q % 20;
        const float* src = (cq < 10) ? (W2l + k * 40 + cq * 4)
                                     : (W2r + k * 40 + (cq - 10) * 4);
        float4 v = *(const float4*)src;
        __half2 h01 = __floats2half2_rn(v.x, v.y);
        __half2 h23 = __floats2half2_rn(v.z, v.w);
        ((uint32_t*)(g_w2h + k * 80 + cq * 4))[0] = *reinterpret_cast<uint32_t*>(&h01);
        ((uint32_t*)(g_w2h + k * 80 + cq * 4))[1] = *reinterpret_cast<uint32_t*>(&h23);
    }
}

// g_deg is zero here (module load / re-zeroed by k_scan every call)
__global__ void k_hist(const void* __restrict__ ei, int E, int N) {
    __shared__ int s_flag;
    int is64 = detect_is64(ei, E, N, threadIdx.x, &s_flag);
    int half = (E + 1) >> 1;
    int e = blockIdx.x * blockDim.x + threadIdx.x;
    int d0 = -1, d1 = -1;
    if (e < half)        d0 = min(max(load_idx2(ei, E + e, is64), 0), N - 1);
    if (e + half < E)    d1 = min(max(load_idx2(ei, E + e + half, is64), 0), N - 1);
    if (d0 >= 0) atomicAdd(&g_deg[d0], 1);
    if (d1 >= 0) atomicAdd(&g_deg[d1], 1);
}

// ---- single-pass scan with decoupled block-sum lookback ----
__global__ void k_scan(int n) {
    const int tid = threadIdx.x, lane = tid & 31, wid = tid >> 5;
    const int bid = blockIdx.x;
    __shared__ int wsum[32];
    __shared__ int s_off;
    int idx = bid * SCAN_CHUNK + tid * 4;
    int v0 = 0, v1 = 0, v2 = 0, v3 = 0;
    if (idx + 0 < n) { v0 = g_deg[idx + 0]; g_deg[idx + 0] = 0; }
    if (idx + 1 < n) { v1 = g_deg[idx + 1]; g_deg[idx + 1] = 0; }
    if (idx + 2 < n) { v2 = g_deg[idx + 2]; g_deg[idx + 2] = 0; }
    if (idx + 3 < n) { v3 = g_deg[idx + 3]; g_deg[idx + 3] = 0; }
    int s = v0 + v1 + v2 + v3;
    int sc = s;
    #pragma unroll
    for (int d = 1; d < 32; d <<= 1) {
        int t = __shfl_up_sync(0xffffffffu, sc, d);
        if (lane >= d) sc += t;
    }
    if (lane == 31) wsum[wid] = sc;
    __syncthreads();
    if (wid == 0) {
        int ws = wsum[lane];
        #pragma unroll
        for (int d = 1; d < 32; d <<= 1) {
            int t = __shfl_up_sync(0xffffffffu, ws, d);
            if (lane >= d) ws += t;
        }
        wsum[lane] = ws;
    }
    __syncthreads();
    int warp_excl = (wid == 0) ? 0 : wsum[wid - 1];
    int excl = warp_excl + (sc - s);

    if (tid == 1023) {
        g_bsum[bid] = warp_excl + sc;
        __threadfence();
        atomicExch(&g_bflag[bid], 1);
    }
    if (tid < 32) {
        int acc = 0;
        for (int j = lane; j < bid; j += 32) {
            while (atomicAdd(&g_bflag[j], 0) == 0) {}
            acc += atomicAdd(&g_bsum[j], 0);
        }
        #pragma unroll
        for (int d = 16; d > 0; d >>= 1)
            acc += __shfl_down_sync(0xffffffffu, acc, d);
        if (lane == 0) s_off = acc;
    }
    __syncthreads();
    int off = s_off + excl;
    int p0 = off + v0, p1 = p0 + v1, p2 = p1 + v2, p3 = p2 + v3;
    if (idx + 0 < n) g_rowptr[idx + 1] = p0;
    if (idx + 1 < n) g_rowptr[idx + 2] = p1;
    if (idx + 2 < n) g_rowptr[idx + 3] = p2;
    if (idx + 3 < n) g_rowptr[idx + 4] = p3;
    if (bid == 0 && tid == 0) g_rowptr[0] = 0;
}

// g_cur is zero here (module load / reset by final k_finish2)
__global__ void k_fill(const void* __restrict__ ei, int E, int N) {
    __shared__ int s_flag;
    int is64 = detect_is64(ei, E, N, threadIdx.x, &s_flag);
    if (blockIdx.x == 0 && threadIdx.x < 32) g_bflag[threadIdx.x] = 0;
    int half = (E + 1) >> 1;
    int e = blockIdx.x * blockDim.x + threadIdx.x;
    if (e < half) {
        int dst = min(max(load_idx2(ei, E + e, is64), 0), N - 1);
        int src = min(max(load_idx2(ei, e, is64), 0), N - 1);
        int pos = g_rowptr[dst] + atomicAdd(&g_cur[dst], 1);
        if (pos < E) g_adj[pos] = src;
    }
    if (e + half < E) {
        int dst = min(max(load_idx2(ei, E + e + half, is64), 0), N - 1);
        int src = min(max(load_idx2(ei, e + half, is64), 0), N - 1);
        int pos = g_rowptr[dst] + atomicAdd(&g_cur[dst], 1);
        if (pos < E) g_adj[pos] = src;
    }
}

// ------------- GEMM1, persistent, 2-pass fp16: T1 = X @ [W1l|W1r] ------------
// D = xhi@w + xlo@w  (x exact-split; only W rounded once -> rel err ~1.5e-4).
// 128-row tile, 256 threads (8 warps = 2m x 4n, warp tile 64x32); W single copy
// resident in smem. smem = 104.5KB -> 2 CTA/SM.
#define GEMM1_SMEM ((128 + 2 * 128) * PADW * 2)

__global__ void __launch_bounds__(256, 2)
k_gemm1_wmma(const float* __restrict__ X, float* __restrict__ T, int n) {
    extern __shared__ char smraw[];
    __half* Wh  = (__half*)smraw;                 // [128][PADW]
    __half* Ahi = Wh + 128 * PADW;                // [128][PADW]
    __half* Alo = Ahi + 128 * PADW;
    const int tid = threadIdx.x, wid = tid >> 5;

    // W resident: 128x128 fp16 = 2048 uint4
    #pragma unroll
    for (int it = 0; it < 8; it++) {
        int p = it * 256 + tid;
        int k = p >> 4, c = p & 15;
        *(uint4*)(Wh + k * PADW + c * 8) = ((const uint4*)g_w1h)[p];
    }

    const int m0 = (wid & 1) * 64;          // 2 m-positions of 64 rows
    const int n0 = (wid >> 1) * 32;         // 4 n-positions of 32 cols
    const int ntiles = (n + 127) >> 7;

    for (int t = blockIdx.x; t < ntiles; t += gridDim.x) {
        const int row0 = t << 7;
        __syncthreads();               // prev tile readers done (orders W on 1st iter)
        // convert X tile (128 rows x 128 cols): 4096 float4 slots
        #pragma unroll 4
        for (int it = 0; it < 16; it++) {
            int p = it * 256 + tid;
            int r = p >> 5, cq = p & 31;
            float4 v = make_float4(0.f, 0.f, 0.f, 0.f);
            if (row0 + r < n) v = ((const float4*)(X + (size_t)(row0 + r) * 128))[cq];
            uint32_t hi2[2], lo2[2];
            split4h(v, hi2, lo2);
            uint32_t* ah = (uint32_t*)(Ahi + r * PADW + cq * 4);
            uint32_t* al = (uint32_t*)(Alo + r * PADW + cq * 4);
            ah[0] = hi2[0]; ah[1] = hi2[1];
            al[0] = lo2[0]; al[1] = lo2[1];
        }
        __syncthreads();

        wmma::fragment<wmma::accumulator, 16, 16, 16, float> acc[4][2];
        #pragma unroll
        for (int r = 0; r < 4; r++)
            #pragma unroll
            for (int c = 0; c < 2; c++) wmma::fill_fragment(acc[r][c], 0.f);

        #pragma unroll
        for (int k = 0; k < 128; k += 16) {
            wmma::fragment<wmma::matrix_b, 16, 16, 16, __half, wmma::row_major> b[2];
            wmma::load_matrix_sync(b[0], Wh + k * PADW + n0,      PADW);
            wmma::load_matrix_sync(b[1], Wh + k * PADW + n0 + 16, PADW);
            wmma::fragment<wmma::matrix_a, 16, 16, 16, __half, wmma::row_major> ah[4];
            #pragma unroll
            for (int r = 0; r < 4; r++)
                wmma::load_matrix_sync(ah[r], Ahi + (m0 + r * 16) * PADW + k, PADW);
            #pragma unroll
            for (int r = 0; r < 4; r++) {
                wmma::mma_sync(acc[r][0], ah[r], b[0], acc[r][0]);
                wmma::mma_sync(acc[r][1], ah[r], b[1], acc[r][1]);
            }
            #pragma unroll
            for (int r = 0; r < 4; r++) {
                wmma::fragment<wmma::matrix_a, 16, 16, 16, __half, wmma::row_major> al;
                wmma::load_matrix_sync(al, Alo + (m0 + r * 16) * PADW + k, PADW);
                wmma::mma_sync(acc[r][0], al, b[0], acc[r][0]);
                wmma::mma_sync(acc[r][1], al, b[1], acc[r][1]);
            }
        }

        // direct global stores (g_t1 padded by 256 rows)
        #pragma unroll
        for (int r = 0; r < 4; r++)
            #pragma unroll
            for (int c = 0; c < 2; c++)
                wmma::store_matrix_sync(T + (size_t)(row0 + m0 + r * 16) * 128 + n0 + c * 16,
                                        acc[r][c], 128, wmma::mem_row_major);
    }
}

// -------- finish layer1: gather t1 + mean + bias + sigmoid -> h (fp16 hi/lo) ---
__global__ void k_finish1(const float* __restrict__ T, const float* __restrict__ bias,
                          int n) {
    int gid = blockIdx.x * blockDim.x + threadIdx.x;     // node*16 + q
    int node = gid >> 4;
    int q = gid & 15;
    if (node >= n) return;
    int s = g_rowptr[node], e = g_rowptr[node + 1];
    float4 a0 = make_float4(0.f, 0.f, 0.f, 0.f);
    float4 a1 = make_float4(0.f, 0.f, 0.f, 0.f);
    int p = s;
    for (; p + 1 < e; p += 2) {
        int j0 = g_adj[p], j1 = g_adj[p + 1];
        float4 v0 = *(const float4*)(T + (size_t)j0 * 128 + q * 4);
        float4 v1 = *(const float4*)(T + (size_t)j1 * 128 + q * 4);
        a0.x += v0.x; a0.y += v0.y; a0.z += v0.z; a0.w += v0.w;
        a1.x += v1.x; a1.y += v1.y; a1.z += v1.z; a1.w += v1.w;
    }
    if (p < e) {
        int j = g_adj[p];
        float4 v = *(const float4*)(T + (size_t)j * 128 + q * 4);
        a0.x += v.x; a0.y += v.y; a0.z += v.z; a0.w += v.w;
    }
    a0.x += a1.x; a0.y += a1.y; a0.z += a1.z; a0.w += a1.w;
    float inv = 1.f / fmaxf((float)(e - s), 1.f);
    float4 r = *(const float4*)(T + (size_t)node * 128 + 64 + q * 4);
    float4 b = *(const float4*)(bias + q * 4);
    float4 o;
    o.x = fmaf(a0.x, inv, r.x + b.x);
    o.y = fmaf(a0.y, inv, r.y + b.y);
    o.z = fmaf(a0.z, inv, r.z + b.z);
    o.w = fmaf(a0.w, inv, r.w + b.w);
    o.x = 1.f / (1.f + expf(-o.x));
    o.y = 1.f / (1.f + expf(-o.y));
    o.z = 1.f / (1.f + expf(-o.z));
    o.w = 1.f / (1.f + expf(-o.w));
    uint32_t hi2[2], lo2[2];
    split4h(o, hi2, lo2);
    *(uint2*)(g_hhi + (size_t)node * 64 + q * 4) = make_uint2(hi2[0], hi2[1]);
    *(uint2*)(g_hlo + (size_t)node * 64 + q * 4) = make_uint2(lo2[0], lo2[1]);
}

// ------------- GEMM2, persistent, 2-pass fp16: T2 = H @ [W2l|W2r] -------------
#define GEMM2_SMEM ((64 * PADB2 + 2 * 128 * PADA2) * 2)

__global__ void __launch_bounds__(320, 2)
k_gemm2_wmma(float* __restrict__ T, int n) {
    extern __shared__ char smraw[];
    __half* Wh  = (__half*)smraw;                  // [64][PADB2]
    __half* Ahi = Wh + 64 * PADB2;                 // [128][PADA2]
    __half* Alo = Ahi + 128 * PADA2;
    const int tid = threadIdx.x, wid = tid >> 5;

    for (int p = tid; p < 640; p += 320) {
        int k = p / 10, c = p % 10;
        *(uint4*)(Wh + k * PADB2 + c * 8) = ((const uint4*)g_w2h)[p];
    }

    const int n0 = (wid % 5) * 16;
    const int m0 = (wid / 5) * 64;
    const int ntiles = (n + 127) >> 7;

    for (int t = blockIdx.x; t < ntiles; t += gridDim.x) {
        const int row0 = t << 7;
        __syncthreads();
        for (int p = tid; p < 2048; p += 320) {
            int r = p >> 4, cq = p & 15;
            uint2 hv = make_uint2(0u, 0u), lv = make_uint2(0u, 0u);
            if (row0 + r < n) {
                hv = *(const uint2*)(g_hhi + (size_t)(row0 + r) * 64 + cq * 4);
                lv = *(const uint2*)(g_hlo + (size_t)(row0 + r) * 64 + cq * 4);
            }
            *(uint2*)(Ahi + r * PADA2 + cq * 4) = hv;
            *(uint2*)(Alo + r * PADA2 + cq * 4) = lv;
        }
        __syncthreads();

        wmma::fragment<wmma::accumulator, 16, 16, 16, float> acc[4];
        #pragma unroll
        for (int r = 0; r < 4; r++) wmma::fill_fragment(acc[r], 0.f);

        #pragma unroll
        for (int k = 0; k < 64; k += 16) {
            wmma::fragment<wmma::matrix_b, 16, 16, 16, __half, wmma::row_major> b;
            wmma::load_matrix_sync(b, Wh + k * PADB2 + n0, PADB2);
            #pragma unroll
            for (int r = 0; r < 4; r++) {
                wmma::fragment<wmma::matrix_a, 16, 16, 16, __half, wmma::row_major> ah, al;
                wmma::load_matrix_sync(ah, Ahi + (m0 + r * 16) * PADA2 + k, PADA2);
                wmma::load_matrix_sync(al, Alo + (m0 + r * 16) * PADA2 + k, PADA2);
                wmma::mma_sync(acc[r], ah, b, acc[r]);
                wmma::mma_sync(acc[r], al, b, acc[r]);
            }
        }

        #pragma unroll
        for (int r = 0; r < 4; r++)
            wmma::store_matrix_sync(T + (size_t)(row0 + m0 + r * 16) * 80 + n0,
                                    acc[r], 80, wmma::mem_row_major);
    }
}

// -------- final: aggregate t2 + mean + residual + bias --------
__global__ void k_finish2(const float* __restrict__ T, const float* __restrict__ bias,
                          float* __restrict__ out, int n) {
    constexpr int Q = 10;
    int gid = blockIdx.x * blockDim.x + threadIdx.x;
    int node = gid / Q;
    int q = gid - node * Q;
    if (node >= n) return;
    int s = g_rowptr[node], e = g_rowptr[node + 1];
    float4 a0 = make_float4(0.f, 0.f, 0.f, 0.f);
    float4 a1 = make_float4(0.f, 0.f, 0.f, 0.f);
    int p = s;
    for (; p + 1 < e; p += 2) {
        int j0 = g_adj[p], j1 = g_adj[p + 1];
        float4 v0 = *(const float4*)(T + (size_t)j0 * 80 + q * 4);
        float4 v1 = *(const float4*)(T + (size_t)j1 * 80 + q * 4);
        a0.x += v0.x; a0.y += v0.y; a0.z += v0.z; a0.w += v0.w;
        a1.x += v1.x; a1.y += v1.y; a1.z += v1.z; a1.w += v1.w;
    }
    if (p < e) {
        int j = g_adj[p];
        float4 v = *(const float4*)(T + (size_t)j * 80 + q * 4);
        a0.x += v.x; a0.y += v.y; a0.z += v.z; a0.w += v.w;
    }
    a0.x += a1.x; a0.y += a1.y; a0.z += a1.z; a0.w += a1.w;
    float inv = 1.f / fmaxf((float)(e - s), 1.f);
    float4 r = *(const float4*)(T + (size_t)node * 80 + 40 + q * 4);
    float4 b = *(const float4*)(bias + q * 4);
    float4 o;
    o.x = fmaf(a0.x, inv, r.x + b.x);
    o.y = fmaf(a0.y, inv, r.y + b.y);
    o.z = fmaf(a0.z, inv, r.z + b.z);
    o.w = fmaf(a0.w, inv, r.w + b.w);
    *(float4*)(out + (size_t)node * 40 + q * 4) = o;
    if (q == 0) g_cur[node] = 0;   // reset for next call
}

// ---------------- launch ----------------
extern "C" void kernel_launch(void* const* d_in, const int* in_sizes, int n_in,
                              void* d_out, int out_size) {
    const float* x   = (const float*)d_in[0];
    const void*  ei  = d_in[1];
    const float* W1l = (const float*)d_in[2];
    const float* b1  = (const float*)d_in[3];
    const float* W1r = (const float*)d_in[4];
    const float* W2l = (const float*)d_in[5];
    const float* b2  = (const float*)d_in[6];
    const float* W2r = (const float*)d_in[7];
    float* out = (float*)d_out;

    const int N = in_sizes[0] / NFEAT;
    const int E = in_sizes[1] / 2;
    const int NB = (N + SCAN_CHUNK - 1) / SCAN_CHUNK;
    const int EH = ((E + 1) / 2 + 255) / 256;

    void *t1p, *t2p;
    cudaGetSymbolAddress(&t1p, g_t1);
    cudaGetSymbolAddress(&t2p, g_t2);

    cudaFuncSetAttribute(k_gemm1_wmma, cudaFuncAttributeMaxDynamicSharedMemorySize, GEMM1_SMEM);
    cudaFuncSetAttribute(k_gemm2_wmma, cudaFuncAttributeMaxDynamicSharedMemorySize, GEMM2_SMEM);

    int g1 = 296;                          // 2 CTA/SM persistent
    int nt1 = (N + 127) / 128;
    if (g1 > nt1) g1 = nt1;
    int g2 = 296;
    if (g2 > (N + 127) / 128) g2 = (N + 127) / 128;

    // fork: side stream = weights + GEMM1; main stream = graph build
    cudaEventRecord(g_evFork, 0);
    cudaStreamWaitEvent(g_s2, g_evFork, 0);

    k_wsplit_all<<<21, 256, 0, g_s2>>>(W1l, W1r, W2l, W2r);          // #1
    k_hist<<<EH, 256>>>(ei, E, N);                                   // #2
    k_scan<<<NB, 1024>>>(N);                                         // #3
    k_gemm1_wmma<<<g1, 256, GEMM1_SMEM, g_s2>>>(x, (float*)t1p, N);  // #4
    k_fill<<<EH, 256>>>(ei, E, N);                                   // #5

    // join
    cudaEventRecord(g_evG1, g_s2);
    cudaStreamWaitEvent(0, g_evG1, 0);

    // tail
    int tot1 = N * 16;
    k_finish1<<<(tot1 + 255) / 256, 256>>>((const float*)t1p, b1, N);          // #6
    k_gemm2_wmma<<<g2, 320, GEMM2_SMEM>>>((float*)t2p, N);                     // #7
    int tot2 = N * 10;
    k_finish2<<<(tot2 + 255) / 256, 256>>>((const float*)t2p, b2, out, N);     // #8
}

// round 15
// speedup vs baseline: 1.3372x; 1.1447x over previous
#include <cuda_runtime.h>
#include <cuda_fp16.h>
#include <mma.h>
#include <math.h>
#include <stdint.h>

using namespace nvcuda;

#define NFEAT 128
#define HID   64
#define NCLS  40
#define MAXN  100000
#define MAXE  600000
#define SCAN_CHUNK 4096
#define PADW 136                      // gemm1 smem row pad (fp16 elems)
#define PADA2 72                      // gemm2 A row pad (K=64)
#define PADB2 88                      // gemm2 B row pad (N=80)

// ---------------- scratch (padded for unguarded frag stores) -----
__device__ float g_t1[(size_t)(MAXN + 256) * 128];
__device__ float g_t2[(size_t)(MAXN + 128) * 80];
__device__ __half g_hh[(size_t)MAXN * 64];    // hidden, fp16
__device__ __half g_w1h[128 * 128];           // W1 = [W1l|W1r], fp16
__device__ __half g_w2h[64 * 80];             // W2 = [W2l|W2r], fp16
__device__ int   g_deg[MAXN];
__device__ int   g_cur[MAXN];
__device__ int   g_rowptr[MAXN + 1];
__device__ int   g_adj[MAXE];
__device__ int   g_bsum[32];
__device__ int   g_bflag[32];

// ---------------- side stream + events (created once at load) -------
static cudaStream_t g_s2;
static cudaEvent_t  g_evFork, g_evG1;
static struct _StreamInit {
    _StreamInit() {
        cudaStreamCreateWithFlags(&g_s2, cudaStreamNonBlocking);
        cudaEventCreateWithFlags(&g_evFork, cudaEventDisableTiming);
        cudaEventCreateWithFlags(&g_evG1,   cudaEventDisableTiming);
    }
} g_streamInit;

// ---------------- per-block inline dtype detect ----------------
__device__ __forceinline__ int detect_is64(const void* ei, int E, int N,
                                           int tid, int* s_flag) {
    if (tid < 32) {
        int samples = (E < 32) ? E : 32;
        bool bad = false;
        if (tid < samples) {
            long long v = ((const long long*)ei)[tid];
            bad = (v < 0 || v >= (long long)N);
        }
        unsigned m = __ballot_sync(0xffffffffu, bad);
        if (tid == 0) *s_flag = (m == 0u) ? 1 : 0;
    }
    __syncthreads();
    return *s_flag;
}

__device__ __forceinline__ int load_idx2(const void* ei, int pos, int is64) {
    if (is64) return (int)((const long long*)ei)[pos];
    return ((const int*)ei)[pos];
}

// ---------------- combined W convert (fp16): W1, W2 ----------
__global__ void k_wsplit_all(const float* __restrict__ W1l, const float* __restrict__ W1r,
                             const float* __restrict__ W2l, const float* __restrict__ W2r) {
    int p = blockIdx.x * blockDim.x + threadIdx.x;
    if (p < 4096) {                                    // W1: 4096 float4 slots
        int k = p >> 5, cq = p & 31;
        const float* src = (cq < 16) ? (W1l + k * 64 + cq * 4)
                                     : (W1r + k * 64 + (cq - 16) * 4);
        float4 v = *(const float4*)src;
        __half2 h01 = __floats2half2_rn(v.x, v.y);
        __half2 h23 = __floats2half2_rn(v.z, v.w);
        ((uint32_t*)(g_w1h + k * 128 + cq * 4))[0] = *reinterpret_cast<uint32_t*>(&h01);
        ((uint32_t*)(g_w1h + k * 128 + cq * 4))[1] = *reinterpret_cast<uint32_t*>(&h23);
    } else if (p < 4096 + 1280) {                      // W2: 1280 float4 slots
        int q = p - 4096;
        int k = q / 20, cq = q % 20;
        const float* src = (cq < 10) ? (W2l + k * 40 + cq * 4)
                                     : (W2r + k * 40 + (cq - 10) * 4);
        float4 v = *(const float4*)src;
        __half2 h01 = __floats2half2_rn(v.x, v.y);
        __half2 h23 = __floats2half2_rn(v.z, v.w);
        ((uint32_t*)(g_w2h + k * 80 + cq * 4))[0] = *reinterpret_cast<uint32_t*>(&h01);
        ((uint32_t*)(g_w2h + k * 80 + cq * 4))[1] = *reinterpret_cast<uint32_t*>(&h23);
    }
}

// g_deg is zero here (module load / re-zeroed by k_scan every call)
__global__ void k_hist(const void* __restrict__ ei, int E, int N) {
    __shared__ int s_flag;
    int is64 = detect_is64(ei, E, N, threadIdx.x, &s_flag);
    int half = (E + 1) >> 1;
    int e = blockIdx.x * blockDim.x + threadIdx.x;
    int d0 = -1, d1 = -1;
    if (e < half)        d0 = min(max(load_idx2(ei, E + e, is64), 0), N - 1);
    if (e + half < E)    d1 = min(max(load_idx2(ei, E + e + half, is64), 0), N - 1);
    if (d0 >= 0) atomicAdd(&g_deg[d0], 1);
    if (d1 >= 0) atomicAdd(&g_deg[d1], 1);
}

// ---- single-pass scan with decoupled block-sum lookback ----
__global__ void k_scan(int n) {
    const int tid = threadIdx.x, lane = tid & 31, wid = tid >> 5;
    const int bid = blockIdx.x;
    __shared__ int wsum[32];
    __shared__ int s_off;
    int idx = bid * SCAN_CHUNK + tid * 4;
    int v0 = 0, v1 = 0, v2 = 0, v3 = 0;
    if (idx + 0 < n) { v0 = g_deg[idx + 0]; g_deg[idx + 0] = 0; }
    if (idx + 1 < n) { v1 = g_deg[idx + 1]; g_deg[idx + 1] = 0; }
    if (idx + 2 < n) { v2 = g_deg[idx + 2]; g_deg[idx + 2] = 0; }
    if (idx + 3 < n) { v3 = g_deg[idx + 3]; g_deg[idx + 3] = 0; }
    int s = v0 + v1 + v2 + v3;
    int sc = s;
    #pragma unroll
    for (int d = 1; d < 32; d <<= 1) {
        int t = __shfl_up_sync(0xffffffffu, sc, d);
        if (lane >= d) sc += t;
    }
    if (lane == 31) wsum[wid] = sc;
    __syncthreads();
    if (wid == 0) {
        int ws = wsum[lane];
        #pragma unroll
        for (int d = 1; d < 32; d <<= 1) {
            int t = __shfl_up_sync(0xffffffffu, ws, d);
            if (lane >= d) ws += t;
        }
        wsum[lane] = ws;
    }
    __syncthreads();
    int warp_excl = (wid == 0) ? 0 : wsum[wid - 1];
    int excl = warp_excl + (sc - s);

    if (tid == 1023) {
        g_bsum[bid] = warp_excl + sc;
        __threadfence();
        atomicExch(&g_bflag[bid], 1);
    }
    if (tid < 32) {
        int acc = 0;
        for (int j = lane; j < bid; j += 32) {
            while (atomicAdd(&g_bflag[j], 0) == 0) {}
            acc += atomicAdd(&g_bsum[j], 0);
        }
        #pragma unroll
        for (int d = 16; d > 0; d >>= 1)
            acc += __shfl_down_sync(0xffffffffu, acc, d);
        if (lane == 0) s_off = acc;
    }
    __syncthreads();
    int off = s_off + excl;
    int p0 = off + v0, p1 = p0 + v1, p2 = p1 + v2, p3 = p2 + v3;
    if (idx + 0 < n) g_rowptr[idx + 1] = p0;
    if (idx + 1 < n) g_rowptr[idx + 2] = p1;
    if (idx + 2 < n) g_rowptr[idx + 3] = p2;
    if (idx + 3 < n) g_rowptr[idx + 4] = p3;
    if (bid == 0 && tid == 0) g_rowptr[0] = 0;
}

// g_cur is zero here (module load / reset by final k_finish2)
__global__ void k_fill(const void* __restrict__ ei, int E, int N) {
    __shared__ int s_flag;
    int is64 = detect_is64(ei, E, N, threadIdx.x, &s_flag);
    if (blockIdx.x == 0 && threadIdx.x < 32) g_bflag[threadIdx.x] = 0;
    int half = (E + 1) >> 1;
    int e = blockIdx.x * blockDim.x + threadIdx.x;
    if (e < half) {
        int dst = min(max(load_idx2(ei, E + e, is64), 0), N - 1);
        int src = min(max(load_idx2(ei, e, is64), 0), N - 1);
        int pos = g_rowptr[dst] + atomicAdd(&g_cur[dst], 1);
        if (pos < E) g_adj[pos] = src;
    }
    if (e + half < E) {
        int dst = min(max(load_idx2(ei, E + e + half, is64), 0), N - 1);
        int src = min(max(load_idx2(ei, e + half, is64), 0), N - 1);
        int pos = g_rowptr[dst] + atomicAdd(&g_cur[dst], 1);
        if (pos < E) g_adj[pos] = src;
    }
}

// ------------- GEMM1, persistent, 1-pass fp16: T1 = X @ [W1l|W1r] ------------
// x and W each rounded once to fp16 -> combined rel err ~2.7e-4 (<< 1e-3).
// 128-row tile, 256 threads (8 warps = 2m x 4n, warp tile 64x32); W resident.
// smem = 69.6KB -> 2 CTA/SM.
#define GEMM1_SMEM ((128 + 128) * PADW * 2)

__global__ void __launch_bounds__(256, 2)
k_gemm1_wmma(const float* __restrict__ X, float* __restrict__ T, int n) {
    extern __shared__ char smraw[];
    __half* Wh = (__half*)smraw;                  // [128][PADW]
    __half* Ah = Wh + 128 * PADW;                 // [128][PADW]
    const int tid = threadIdx.x, wid = tid >> 5;

    // W resident: 128x128 fp16 = 2048 uint4
    #pragma unroll
    for (int it = 0; it < 8; it++) {
        int p = it * 256 + tid;
        int k = p >> 4, c = p & 15;
        *(uint4*)(Wh + k * PADW + c * 8) = ((const uint4*)g_w1h)[p];
    }

    const int m0 = (wid & 1) * 64;          // 2 m-positions of 64 rows
    const int n0 = (wid >> 1) * 32;         // 4 n-positions of 32 cols
    const int ntiles = (n + 127) >> 7;

    for (int t = blockIdx.x; t < ntiles; t += gridDim.x) {
        const int row0 = t << 7;
        __syncthreads();
        // convert X tile (128 rows x 128 cols): 4096 float4 slots
        #pragma unroll 4
        for (int it = 0; it < 16; it++) {
            int p = it * 256 + tid;
            int r = p >> 5, cq = p & 31;
            float4 v = make_float4(0.f, 0.f, 0.f, 0.f);
            if (row0 + r < n) v = ((const float4*)(X + (size_t)(row0 + r) * 128))[cq];
            __half2 h01 = __floats2half2_rn(v.x, v.y);
            __half2 h23 = __floats2half2_rn(v.z, v.w);
            uint32_t* a = (uint32_t*)(Ah + r * PADW + cq * 4);
            a[0] = *reinterpret_cast<uint32_t*>(&h01);
            a[1] = *reinterpret_cast<uint32_t*>(&h23);
        }
        __syncthreads();

        wmma::fragment<wmma::accumulator, 16, 16, 16, float> acc[4][2];
        #pragma unroll
        for (int r = 0; r < 4; r++)
            #pragma unroll
            for (int c = 0; c < 2; c++) wmma::fill_fragment(acc[r][c], 0.f);

        #pragma unroll
        for (int k = 0; k < 128; k += 16) {
            wmma::fragment<wmma::matrix_b, 16, 16, 16, __half, wmma::row_major> b[2];
            wmma::load_matrix_sync(b[0], Wh + k * PADW + n0,      PADW);
            wmma::load_matrix_sync(b[1], Wh + k * PADW + n0 + 16, PADW);
            #pragma unroll
            for (int r = 0; r < 4; r++) {
                wmma::fragment<wmma::matrix_a, 16, 16, 16, __half, wmma::row_major> a;
                wmma::load_matrix_sync(a, Ah + (m0 + r * 16) * PADW + k, PADW);
                wmma::mma_sync(acc[r][0], a, b[0], acc[r][0]);
                wmma::mma_sync(acc[r][1], a, b[1], acc[r][1]);
            }
        }

        // direct global stores (g_t1 padded by 256 rows)
        #pragma unroll
        for (int r = 0; r < 4; r++)
            #pragma unroll
            for (int c = 0; c < 2; c++)
                wmma::store_matrix_sync(T + (size_t)(row0 + m0 + r * 16) * 128 + n0 + c * 16,
                                        acc[r][c], 128, wmma::mem_row_major);
    }
}

// -------- finish layer1: gather t1 + mean + bias + sigmoid -> h (fp16) --------
__global__ void k_finish1(const float* __restrict__ T, const float* __restrict__ bias,
                          int n) {
    int gid = blockIdx.x * blockDim.x + threadIdx.x;     // node*16 + q
    int node = gid >> 4;
    int q = gid & 15;
    if (node >= n) return;
    int s = g_rowptr[node], e = g_rowptr[node + 1];
    float4 a0 = make_float4(0.f, 0.f, 0.f, 0.f);
    float4 a1 = make_float4(0.f, 0.f, 0.f, 0.f);
    int p = s;
    for (; p + 1 < e; p += 2) {
        int j0 = g_adj[p], j1 = g_adj[p + 1];
        float4 v0 = *(const float4*)(T + (size_t)j0 * 128 + q * 4);
        float4 v1 = *(const float4*)(T + (size_t)j1 * 128 + q * 4);
        a0.x += v0.x; a0.y += v0.y; a0.z += v0.z; a0.w += v0.w;
        a1.x += v1.x; a1.y += v1.y; a1.z += v1.z; a1.w += v1.w;
    }
    if (p < e) {
        int j = g_adj[p];
        float4 v = *(const float4*)(T + (size_t)j * 128 + q * 4);
        a0.x += v.x; a0.y += v.y; a0.z += v.z; a0.w += v.w;
    }
    a0.x += a1.x; a0.y += a1.y; a0.z += a1.z; a0.w += a1.w;
    float inv = 1.f / fmaxf((float)(e - s), 1.f);
    float4 r = *(const float4*)(T + (size_t)node * 128 + 64 + q * 4);
    float4 b = *(const float4*)(bias + q * 4);
    float4 o;
    o.x = fmaf(a0.x, inv, r.x + b.x);
    o.y = fmaf(a0.y, inv, r.y + b.y);
    o.z = fmaf(a0.z, inv, r.z + b.z);
    o.w = fmaf(a0.w, inv, r.w + b.w);
    o.x = 1.f / (1.f + expf(-o.x));
    o.y = 1.f / (1.f + expf(-o.y));
    o.z = 1.f / (1.f + expf(-o.z));
    o.w = 1.f / (1.f + expf(-o.w));
    __half2 h01 = __floats2half2_rn(o.x, o.y);
    __half2 h23 = __floats2half2_rn(o.z, o.w);
    *(uint2*)(g_hh + (size_t)node * 64 + q * 4) =
        make_uint2(*reinterpret_cast<uint32_t*>(&h01), *reinterpret_cast<uint32_t*>(&h23));
}

// ------------- GEMM2, persistent, 1-pass fp16: T2 = H @ [W2l|W2r] -------------
#define GEMM2_SMEM ((64 * PADB2 + 128 * PADA2) * 2)

__global__ void __launch_bounds__(320, 2)
k_gemm2_wmma(float* __restrict__ T, int n) {
    extern __shared__ char smraw[];
    __half* Wh = (__half*)smraw;                   // [64][PADB2]
    __half* Ah = Wh + 64 * PADB2;                  // [128][PADA2]
    const int tid = threadIdx.x, wid = tid >> 5;

    for (int p = tid; p < 640; p += 320) {
        int k = p / 10, c = p % 10;
        *(uint4*)(Wh + k * PADB2 + c * 8) = ((const uint4*)g_w2h)[p];
    }

    const int n0 = (wid % 5) * 16;
    const int m0 = (wid / 5) * 64;
    const int ntiles = (n + 127) >> 7;

    for (int t = blockIdx.x; t < ntiles; t += gridDim.x) {
        const int row0 = t << 7;
        __syncthreads();
        for (int p = tid; p < 2048; p += 320) {
            int r = p >> 4, cq = p & 15;
            uint2 hv = make_uint2(0u, 0u);
            if (row0 + r < n)
                hv = *(const uint2*)(g_hh + (size_t)(row0 + r) * 64 + cq * 4);
            *(uint2*)(Ah + r * PADA2 + cq * 4) = hv;
        }
        __syncthreads();

        wmma::fragment<wmma::accumulator, 16, 16, 16, float> acc[4];
        #pragma unroll
        for (int r = 0; r < 4; r++) wmma::fill_fragment(acc[r], 0.f);

        #pragma unroll
        for (int k = 0; k < 64; k += 16) {
            wmma::fragment<wmma::matrix_b, 16, 16, 16, __half, wmma::row_major> b;
            wmma::load_matrix_sync(b, Wh + k * PADB2 + n0, PADB2);
            #pragma unroll
            for (int r = 0; r < 4; r++) {
                wmma::fragment<wmma::matrix_a, 16, 16, 16, __half, wmma::row_major> a;
                wmma::load_matrix_sync(a, Ah + (m0 + r * 16) * PADA2 + k, PADA2);
                wmma::mma_sync(acc[r], a, b, acc[r]);
            }
        }

        #pragma unroll
        for (int r = 0; r < 4; r++)
            wmma::store_matrix_sync(T + (size_t)(row0 + m0 + r * 16) * 80 + n0,
                                    acc[r], 80, wmma::mem_row_major);
    }
}

// -------- final: aggregate t2 + mean + residual + bias --------
__global__ void k_finish2(const float* __restrict__ T, const float* __restrict__ bias,
                          float* __restrict__ out, int n) {
    constexpr int Q = 10;
    int gid = blockIdx.x * blockDim.x + threadIdx.x;
    int node = gid / Q;
    int q = gid - node * Q;
    if (node >= n) return;
    int s = g_rowptr[node], e = g_rowptr[node + 1];
    float4 a0 = make_float4(0.f, 0.f, 0.f, 0.f);
    float4 a1 = make_float4(0.f, 0.f, 0.f, 0.f);
    int p = s;
    for (; p + 1 < e; p += 2) {
        int j0 = g_adj[p], j1 = g_adj[p + 1];
        float4 v0 = *(const float4*)(T + (size_t)j0 * 80 + q * 4);
        float4 v1 = *(const float4*)(T + (size_t)j1 * 80 + q * 4);
        a0.x += v0.x; a0.y += v0.y; a0.z += v0.z; a0.w += v0.w;
        a1.x += v1.x; a1.y += v1.y; a1.z += v1.z; a1.w += v1.w;
    }
    if (p < e) {
        int j = g_adj[p];
        float4 v = *(const float4*)(T + (size_t)j * 80 + q * 4);
        a0.x += v.x; a0.y += v.y; a0.z += v.z; a0.w += v.w;
    }
    a0.x += a1.x; a0.y += a1.y; a0.z += a1.z; a0.w += a1.w;
    float inv = 1.f / fmaxf((float)(e - s), 1.f);
    float4 r = *(const float4*)(T + (size_t)node * 80 + 40 + q * 4);
    float4 b = *(const float4*)(bias + q * 4);
    float4 o;
    o.x = fmaf(a0.x, inv, r.x + b.x);
    o.y = fmaf(a0.y, inv, r.y + b.y);
    o.z = fmaf(a0.z, inv, r.z + b.z);
    o.w = fmaf(a0.w, inv, r.w + b.w);
    *(float4*)(out + (size_t)node * 40 + q * 4) = o;
    if (q == 0) g_cur[node] = 0;   // reset for next call
}

// ---------------- launch ----------------
extern "C" void kernel_launch(void* const* d_in, const int* in_sizes, int n_in,
                              void* d_out, int out_size) {
    const float* x   = (const float*)d_in[0];
    const void*  ei  = d_in[1];
    const float* W1l = (const float*)d_in[2];
    const float* b1  = (const float*)d_in[3];
    const float* W1r = (const float*)d_in[4];
    const float* W2l = (const float*)d_in[5];
    const float* b2  = (const float*)d_in[6];
    const float* W2r = (const float*)d_in[7];
    float* out = (float*)d_out;

    const int N = in_sizes[0] / NFEAT;
    const int E = in_sizes[1] / 2;
    const int NB = (N + SCAN_CHUNK - 1) / SCAN_CHUNK;
    const int EH = ((E + 1) / 2 + 255) / 256;

    void *t1p, *t2p;
    cudaGetSymbolAddress(&t1p, g_t1);
    cudaGetSymbolAddress(&t2p, g_t2);

    cudaFuncSetAttribute(k_gemm1_wmma, cudaFuncAttributeMaxDynamicSharedMemorySize, GEMM1_SMEM);
    cudaFuncSetAttribute(k_gemm2_wmma, cudaFuncAttributeMaxDynamicSharedMemorySize, GEMM2_SMEM);

    int g1 = 296;                          // 2 CTA/SM persistent
    int nt1 = (N + 127) / 128;
    if (g1 > nt1) g1 = nt1;
    int g2 = 296;
    if (g2 > (N + 127) / 128) g2 = (N + 127) / 128;

    // fork: side stream = weights + GEMM1; main stream = graph build
    cudaEventRecord(g_evFork, 0);
    cudaStreamWaitEvent(g_s2, g_evFork, 0);

    k_wsplit_all<<<21, 256, 0, g_s2>>>(W1l, W1r, W2l, W2r);          // #1
    k_hist<<<EH, 256>>>(ei, E, N);                                   // #2
    k_scan<<<NB, 1024>>>(N);                                         // #3
    k_gemm1_wmma<<<g1, 256, GEMM1_SMEM, g_s2>>>(x, (float*)t1p, N);  // #4
    k_fill<<<EH, 256>>>(ei, E, N);                                   // #5

    // join
    cudaEventRecord(g_evG1, g_s2);
    cudaStreamWaitEvent(0, g_evG1, 0);

    // tail
    int tot1 = N * 16;
    k_finish1<<<(tot1 + 255) / 256, 256>>>((const float*)t1p, b1, N);          // #6
    k_gemm2_wmma<<<g2, 320, GEMM2_SMEM>>>((float*)t2p, N);                     // #7
    int tot2 = N * 10;
    k_finish2<<<(tot2 + 255) / 256, 256>>>((const float*)t2p, b2, out, N);     // #8
}

// round 16
// speedup vs baseline: 1.3380x; 1.0006x over previous
#include <cuda_runtime.h>
#include <cuda_fp16.h>
#include <mma.h>
#include <math.h>
#include <stdint.h>

using namespace nvcuda;

#define NFEAT 128
#define HID   64
#define NCLS  40
#define MAXN  100000
#define MAXE  600000
#define SCAN_CHUNK 4096
#define PADW 136                      // gemm1 smem row pad (fp16 elems)
#define PADA2 72                      // gemm2 A row pad (K=64)
#define PADB2 88                      // gemm2 B row pad (N=80)

// ---------------- scratch (padded for unguarded frag stores) -----
__device__ __half g_t1h[(size_t)(MAXN + 256) * 128];   // [x@W1l | x@W1r] fp16
__device__ __half g_t2h[(size_t)(MAXN + 128) * 80];    // [h@W2l | h@W2r] fp16
__device__ __half g_hh[(size_t)MAXN * 64];             // hidden, fp16
__device__ __half g_w1h[128 * 128];                    // W1 fp16
__device__ __half g_w2h[64 * 80];                      // W2 fp16
__device__ int   g_deg[MAXN];
__device__ int   g_cur[MAXN];
__device__ int   g_rowptr[MAXN + 1];
__device__ int   g_adj[MAXE];
__device__ int   g_bsum[32];
__device__ int   g_bflag[32];

// ---------------- side stream + events (created once at load) -------
static cudaStream_t g_s2;
static cudaEvent_t  g_evFork, g_evG1;
static struct _StreamInit {
    _StreamInit() {
        cudaStreamCreateWithFlags(&g_s2, cudaStreamNonBlocking);
        cudaEventCreateWithFlags(&g_evFork, cudaEventDisableTiming);
        cudaEventCreateWithFlags(&g_evG1,   cudaEventDisableTiming);
    }
} g_streamInit;

// ---------------- helpers ----------------
__device__ __forceinline__ void addh8(float* a, uint4 u) {
    __half2* h = (__half2*)&u;
    #pragma unroll
    for (int i = 0; i < 4; i++) {
        float2 f = __half22float2(h[i]);
        a[2 * i]     += f.x;
        a[2 * i + 1] += f.y;
    }
}

// convert a 16x16 float accumulator fragment to fp16 and store to global.
// scr: per-warp 16x20 float scratch in smem. ldm_h: dst row length in halves.
template <typename FragT>
__device__ __forceinline__ void frag_store_f16(float* scr, const FragT& acc,
                                               __half* dst, int ldm_h, int lane) {
    wmma::store_matrix_sync(scr, acc, 20, wmma::mem_row_major);
    __syncwarp();
    int r = lane >> 1, c8 = (lane & 1) * 8;
    const float* sp = scr + r * 20 + c8;
    __half2 h0 = __floats2half2_rn(sp[0], sp[1]);
    __half2 h1 = __floats2half2_rn(sp[2], sp[3]);
    __half2 h2 = __floats2half2_rn(sp[4], sp[5]);
    __half2 h3 = __floats2half2_rn(sp[6], sp[7]);
    uint4 v = make_uint4(*reinterpret_cast<uint32_t*>(&h0),
                         *reinterpret_cast<uint32_t*>(&h1),
                         *reinterpret_cast<uint32_t*>(&h2),
                         *reinterpret_cast<uint32_t*>(&h3));
    *(uint4*)(dst + (size_t)r * ldm_h + c8) = v;
    __syncwarp();
}

// ---------------- per-block inline dtype detect ----------------
__device__ __forceinline__ int detect_is64(const void* ei, int E, int N,
                                           int tid, int* s_flag) {
    if (tid < 32) {
        int samples = (E < 32) ? E : 32;
        bool bad = false;
        if (tid < samples) {
            long long v = ((const long long*)ei)[tid];
            bad = (v < 0 || v >= (long long)N);
        }
        unsigned m = __ballot_sync(0xffffffffu, bad);
        if (tid == 0) *s_flag = (m == 0u) ? 1 : 0;
    }
    __syncthreads();
    return *s_flag;
}

__device__ __forceinline__ int load_idx2(const void* ei, int pos, int is64) {
    if (is64) return (int)((const long long*)ei)[pos];
    return ((const int*)ei)[pos];
}

// ---------------- combined W convert (fp16): W1, W2 ----------
__global__ void k_wsplit_all(const float* __restrict__ W1l, const float* __restrict__ W1r,
                             const float* __restrict__ W2l, const float* __restrict__ W2r) {
    int p = blockIdx.x * blockDim.x + threadIdx.x;
    if (p < 4096) {                                    // W1: 4096 float4 slots
        int k = p >> 5, cq = p & 31;
        const float* src = (cq < 16) ? (W1l + k * 64 + cq * 4)
                                     : (W1r + k * 64 + (cq - 16) * 4);
        float4 v = *(const float4*)src;
        __half2 h01 = __floats2half2_rn(v.x, v.y);
        __half2 h23 = __floats2half2_rn(v.z, v.w);
        ((uint32_t*)(g_w1h + k * 128 + cq * 4))[0] = *reinterpret_cast<uint32_t*>(&h01);
        ((uint32_t*)(g_w1h + k * 128 + cq * 4))[1] = *reinterpret_cast<uint32_t*>(&h23);
    } else if (p < 4096 + 1280) {                      // W2: 1280 float4 slots
        int q = p - 4096;
        int k = q / 20, cq = q % 20;
        const float* src = (cq < 10) ? (W2l + k * 40 + cq * 4)
                                     : (W2r + k * 40 + (cq - 10) * 4);
        float4 v = *(const float4*)src;
        __half2 h01 = __floats2half2_rn(v.x, v.y);
        __half2 h23 = __floats2half2_rn(v.z, v.w);
        ((uint32_t*)(g_w2h + k * 80 + cq * 4))[0] = *reinterpret_cast<uint32_t*>(&h01);
        ((uint32_t*)(g_w2h + k * 80 + cq * 4))[1] = *reinterpret_cast<uint32_t*>(&h23);
    }
}

// g_deg is zero here (module load / re-zeroed by k_scan every call)
__global__ void k_hist(const void* __restrict__ ei, int E, int N) {
    __shared__ int s_flag;
    int is64 = detect_is64(ei, E, N, threadIdx.x, &s_flag);
    int half = (E + 1) >> 1;
    int e = blockIdx.x * blockDim.x + threadIdx.x;
    int d0 = -1, d1 = -1;
    if (e < half)        d0 = min(max(load_idx2(ei, E + e, is64), 0), N - 1);
    if (e + half < E)    d1 = min(max(load_idx2(ei, E + e + half, is64), 0), N - 1);
    if (d0 >= 0) atomicAdd(&g_deg[d0], 1);
    if (d1 >= 0) atomicAdd(&g_deg[d1], 1);
}

// ---- single-pass scan with decoupled block-sum lookback ----
__global__ void k_scan(int n) {
    const int tid = threadIdx.x, lane = tid & 31, wid = tid >> 5;
    const int bid = blockIdx.x;
    __shared__ int wsum[32];
    __shared__ int s_off;
    int idx = bid * SCAN_CHUNK + tid * 4;
    int v0 = 0, v1 = 0, v2 = 0, v3 = 0;
    if (idx + 0 < n) { v0 = g_deg[idx + 0]; g_deg[idx + 0] = 0; }
    if (idx + 1 < n) { v1 = g_deg[idx + 1]; g_deg[idx + 1] = 0; }
    if (idx + 2 < n) { v2 = g_deg[idx + 2]; g_deg[idx + 2] = 0; }
    if (idx + 3 < n) { v3 = g_deg[idx + 3]; g_deg[idx + 3] = 0; }
    int s = v0 + v1 + v2 + v3;
    int sc = s;
    #pragma unroll
    for (int d = 1; d < 32; d <<= 1) {
        int t = __shfl_up_sync(0xffffffffu, sc, d);
        if (lane >= d) sc += t;
    }
    if (lane == 31) wsum[wid] = sc;
    __syncthreads();
    if (wid == 0) {
        int ws = wsum[lane];
        #pragma unroll
        for (int d = 1; d < 32; d <<= 1) {
            int t = __shfl_up_sync(0xffffffffu, ws, d);
            if (lane >= d) ws += t;
        }
        wsum[lane] = ws;
    }
    __syncthreads();
    int warp_excl = (wid == 0) ? 0 : wsum[wid - 1];
    int excl = warp_excl + (sc - s);

    if (tid == 1023) {
        g_bsum[bid] = warp_excl + sc;
        __threadfence();
        atomicExch(&g_bflag[bid], 1);
    }
    if (tid < 32) {
        int acc = 0;
        for (int j = lane; j < bid; j += 32) {
            while (atomicAdd(&g_bflag[j], 0) == 0) {}
            acc += atomicAdd(&g_bsum[j], 0);
        }
        #pragma unroll
        for (int d = 16; d > 0; d >>= 1)
            acc += __shfl_down_sync(0xffffffffu, acc, d);
        if (lane == 0) s_off = acc;
    }
    __syncthreads();
    int off = s_off + excl;
    int p0 = off + v0, p1 = p0 + v1, p2 = p1 + v2, p3 = p2 + v3;
    if (idx + 0 < n) g_rowptr[idx + 1] = p0;
    if (idx + 1 < n) g_rowptr[idx + 2] = p1;
    if (idx + 2 < n) g_rowptr[idx + 3] = p2;
    if (idx + 3 < n) g_rowptr[idx + 4] = p3;
    if (bid == 0 && tid == 0) g_rowptr[0] = 0;
}

// g_cur is zero here (module load / reset by final k_finish2)
__global__ void k_fill(const void* __restrict__ ei, int E, int N) {
    __shared__ int s_flag;
    int is64 = detect_is64(ei, E, N, threadIdx.x, &s_flag);
    if (blockIdx.x == 0 && threadIdx.x < 32) g_bflag[threadIdx.x] = 0;
    int half = (E + 1) >> 1;
    int e = blockIdx.x * blockDim.x + threadIdx.x;
    if (e < half) {
        int dst = min(max(load_idx2(ei, E + e, is64), 0), N - 1);
        int src = min(max(load_idx2(ei, e, is64), 0), N - 1);
        int pos = g_rowptr[dst] + atomicAdd(&g_cur[dst], 1);
        if (pos < E) g_adj[pos] = src;
    }
    if (e + half < E) {
        int dst = min(max(load_idx2(ei, E + e + half, is64), 0), N - 1);
        int src = min(max(load_idx2(ei, e + half, is64), 0), N - 1);
        int pos = g_rowptr[dst] + atomicAdd(&g_cur[dst], 1);
        if (pos < E) g_adj[pos] = src;
    }
}

// ------------- GEMM1, persistent, fp16 in/out: T1h = X @ [W1l|W1r] ------------
// smem: W(34816) + A(34816) + scratch(8x1280x4=10240... floats) layout below.
#define G1_SCR_OFF (2 * 128 * PADW * 2)
#define GEMM1_SMEM (G1_SCR_OFF + 8 * 320 * 4)

__global__ void __launch_bounds__(256, 2)
k_gemm1_wmma(const float* __restrict__ X, __half* __restrict__ T, int n) {
    extern __shared__ char smraw[];
    __half* Wh = (__half*)smraw;                  // [128][PADW]
    __half* Ah = Wh + 128 * PADW;                 // [128][PADW]
    const int tid = threadIdx.x, wid = tid >> 5, lane = tid & 31;
    float* scr = (float*)(smraw + G1_SCR_OFF) + wid * 320;

    // W resident: 128x128 fp16 = 2048 uint4
    #pragma unroll
    for (int it = 0; it < 8; it++) {
        int p = it * 256 + tid;
        int k = p >> 4, c = p & 15;
        *(uint4*)(Wh + k * PADW + c * 8) = ((const uint4*)g_w1h)[p];
    }

    const int m0 = (wid & 1) * 64;          // 2 m-positions of 64 rows
    const int n0 = (wid >> 1) * 32;         // 4 n-positions of 32 cols
    const int ntiles = (n + 127) >> 7;

    for (int t = blockIdx.x; t < ntiles; t += gridDim.x) {
        const int row0 = t << 7;
        __syncthreads();
        // convert X tile (128 rows x 128 cols): 4096 float4 slots
        #pragma unroll 4
        for (int it = 0; it < 16; it++) {
            int p = it * 256 + tid;
            int r = p >> 5, cq = p & 31;
            float4 v = make_float4(0.f, 0.f, 0.f, 0.f);
            if (row0 + r < n) v = ((const float4*)(X + (size_t)(row0 + r) * 128))[cq];
            __half2 h01 = __floats2half2_rn(v.x, v.y);
            __half2 h23 = __floats2half2_rn(v.z, v.w);
            uint32_t* a = (uint32_t*)(Ah + r * PADW + cq * 4);
            a[0] = *reinterpret_cast<uint32_t*>(&h01);
            a[1] = *reinterpret_cast<uint32_t*>(&h23);
        }
        __syncthreads();

        wmma::fragment<wmma::accumulator, 16, 16, 16, float> acc[4][2];
        #pragma unroll
        for (int r = 0; r < 4; r++)
            #pragma unroll
            for (int c = 0; c < 2; c++) wmma::fill_fragment(acc[r][c], 0.f);

        #pragma unroll
        for (int k = 0; k < 128; k += 16) {
            wmma::fragment<wmma::matrix_b, 16, 16, 16, __half, wmma::row_major> b[2];
            wmma::load_matrix_sync(b[0], Wh + k * PADW + n0,      PADW);
            wmma::load_matrix_sync(b[1], Wh + k * PADW + n0 + 16, PADW);
            #pragma unroll
            for (int r = 0; r < 4; r++) {
                wmma::fragment<wmma::matrix_a, 16, 16, 16, __half, wmma::row_major> a;
                wmma::load_matrix_sync(a, Ah + (m0 + r * 16) * PADW + k, PADW);
                wmma::mma_sync(acc[r][0], a, b[0], acc[r][0]);
                wmma::mma_sync(acc[r][1], a, b[1], acc[r][1]);
            }
        }

        // fp16 epilogue via per-warp scratch (g_t1h padded by 256 rows)
        #pragma unroll
        for (int r = 0; r < 4; r++)
            #pragma unroll
            for (int c = 0; c < 2; c++)
                frag_store_f16(scr, acc[r][c],
                               T + (size_t)(row0 + m0 + r * 16) * 128 + n0 + c * 16,
                               128, lane);
    }
}

// -------- finish layer1: gather t1h + mean + bias + sigmoid -> h (fp16) -------
// thread = node*8 + q; q covers 8 fp16 values (uint4).
__global__ void k_finish1(const __half* __restrict__ T, const float* __restrict__ bias,
                          int n) {
    int gid = blockIdx.x * blockDim.x + threadIdx.x;
    int node = gid >> 3;
    int q = gid & 7;
    if (node >= n) return;
    int s = g_rowptr[node], e = g_rowptr[node + 1];
    float a0[8] = {0, 0, 0, 0, 0, 0, 0, 0};
    float a1[8] = {0, 0, 0, 0, 0, 0, 0, 0};
    int p = s;
    for (; p + 1 < e; p += 2) {
        int j0 = g_adj[p], j1 = g_adj[p + 1];
        uint4 u0 = *(const uint4*)(T + (size_t)j0 * 128 + q * 8);
        uint4 u1 = *(const uint4*)(T + (size_t)j1 * 128 + q * 8);
        addh8(a0, u0);
        addh8(a1, u1);
    }
    if (p < e) {
        uint4 u = *(const uint4*)(T + (size_t)g_adj[p] * 128 + q * 8);
        addh8(a0, u);
    }
    float inv = 1.f / fmaxf((float)(e - s), 1.f);
    uint4 ru = *(const uint4*)(T + (size_t)node * 128 + 64 + q * 8);
    float rr[8] = {0, 0, 0, 0, 0, 0, 0, 0};
    addh8(rr, ru);
    float4 b0 = *(const float4*)(bias + q * 8);
    float4 b1v = *(const float4*)(bias + q * 8 + 4);
    const float* bb = &b0.x;   // b0,b1v contiguous on stack? use explicit
    float bv[8] = {b0.x, b0.y, b0.z, b0.w, b1v.x, b1v.y, b1v.z, b1v.w};
    float o[8];
    #pragma unroll
    for (int i = 0; i < 8; i++) {
        float v = fmaf(a0[i] + a1[i], inv, rr[i] + bv[i]);
        o[i] = 1.f / (1.f + expf(-v));
    }
    (void)bb;
    __half2 h0 = __floats2half2_rn(o[0], o[1]);
    __half2 h1 = __floats2half2_rn(o[2], o[3]);
    __half2 h2 = __floats2half2_rn(o[4], o[5]);
    __half2 h3 = __floats2half2_rn(o[6], o[7]);
    *(uint4*)(g_hh + (size_t)node * 64 + q * 8) =
        make_uint4(*reinterpret_cast<uint32_t*>(&h0), *reinterpret_cast<uint32_t*>(&h1),
                   *reinterpret_cast<uint32_t*>(&h2), *reinterpret_cast<uint32_t*>(&h3));
}

// ------------- GEMM2, persistent, fp16 in/out: T2h = H @ [W2l|W2r] ------------
#define G2_SCR_OFF ((64 * PADB2 + 128 * PADA2) * 2)
#define GEMM2_SMEM (G2_SCR_OFF + 10 * 320 * 4)

__global__ void __launch_bounds__(320, 2)
k_gemm2_wmma(__half* __restrict__ T, int n) {
    extern __shared__ char smraw[];
    __half* Wh = (__half*)smraw;                   // [64][PADB2]
    __half* Ah = Wh + 64 * PADB2;                  // [128][PADA2]
    const int tid = threadIdx.x, wid = tid >> 5, lane = tid & 31;
    float* scr = (float*)(smraw + G2_SCR_OFF) + wid * 320;

    for (int p = tid; p < 640; p += 320) {
        int k = p / 10, c = p % 10;
        *(uint4*)(Wh + k * PADB2 + c * 8) = ((const uint4*)g_w2h)[p];
    }

    const int n0 = (wid % 5) * 16;
    const int m0 = (wid / 5) * 64;
    const int ntiles = (n + 127) >> 7;

    for (int t = blockIdx.x; t < ntiles; t += gridDim.x) {
        const int row0 = t << 7;
        __syncthreads();
        for (int p = tid; p < 2048; p += 320) {
            int r = p >> 4, cq = p & 15;
            uint2 hv = make_uint2(0u, 0u);
            if (row0 + r < n)
                hv = *(const uint2*)(g_hh + (size_t)(row0 + r) * 64 + cq * 4);
            *(uint2*)(Ah + r * PADA2 + cq * 4) = hv;
        }
        __syncthreads();

        wmma::fragment<wmma::accumulator, 16, 16, 16, float> acc[4];
        #pragma unroll
        for (int r = 0; r < 4; r++) wmma::fill_fragment(acc[r], 0.f);

        #pragma unroll
        for (int k = 0; k < 64; k += 16) {
            wmma::fragment<wmma::matrix_b, 16, 16, 16, __half, wmma::row_major> b;
            wmma::load_matrix_sync(b, Wh + k * PADB2 + n0, PADB2);
            #pragma unroll
            for (int r = 0; r < 4; r++) {
                wmma::fragment<wmma::matrix_a, 16, 16, 16, __half, wmma::row_major> a;
                wmma::load_matrix_sync(a, Ah + (m0 + r * 16) * PADA2 + k, PADA2);
                wmma::mma_sync(acc[r], a, b, acc[r]);
            }
        }

        #pragma unroll
        for (int r = 0; r < 4; r++)
            frag_store_f16(scr, acc[r],
                           T + (size_t)(row0 + m0 + r * 16) * 80 + n0, 80, lane);
    }
}

// -------- final: aggregate t2h + mean + residual + bias -> out (fp32) --------
// thread = node*5 + q; q covers 8 fp16 values.
__global__ void k_finish2(const __half* __restrict__ T, const float* __restrict__ bias,
                          float* __restrict__ out, int n) {
    int gid = blockIdx.x * blockDim.x + threadIdx.x;
    int node = gid / 5;
    int q = gid - node * 5;
    if (node >= n) return;
    int s = g_rowptr[node], e = g_rowptr[node + 1];
    float a0[8] = {0, 0, 0, 0, 0, 0, 0, 0};
    float a1[8] = {0, 0, 0, 0, 0, 0, 0, 0};
    int p = s;
    for (; p + 1 < e; p += 2) {
        int j0 = g_adj[p], j1 = g_adj[p + 1];
        uint4 u0 = *(const uint4*)(T + (size_t)j0 * 80 + q * 8);
        uint4 u1 = *(const uint4*)(T + (size_t)j1 * 80 + q * 8);
        addh8(a0, u0);
        addh8(a1, u1);
    }
    if (p < e) {
        uint4 u = *(const uint4*)(T + (size_t)g_adj[p] * 80 + q * 8);
        addh8(a0, u);
    }
    float inv = 1.f / fmaxf((float)(e - s), 1.f);
    uint4 ru = *(const uint4*)(T + (size_t)node * 80 + 40 + q * 8);
    float rr[8] = {0, 0, 0, 0, 0, 0, 0, 0};
    addh8(rr, ru);
    float4 b0 = *(const float4*)(bias + q * 8);
    float4 b1v = *(const float4*)(bias + q * 8 + 4);
    float bv[8] = {b0.x, b0.y, b0.z, b0.w, b1v.x, b1v.y, b1v.z, b1v.w};
    float o[8];
    #pragma unroll
    for (int i = 0; i < 8; i++)
        o[i] = fmaf(a0[i] + a1[i], inv, rr[i] + bv[i]);
    float* dst = out + (size_t)node * 40 + q * 8;
    *(float4*)(dst + 0) = make_float4(o[0], o[1], o[2], o[3]);
    *(float4*)(dst + 4) = make_float4(o[4], o[5], o[6], o[7]);
    if (q == 0) g_cur[node] = 0;   // reset for next call
}

// ---------------- launch ----------------
extern "C" void kernel_launch(void* const* d_in, const int* in_sizes, int n_in,
                              void* d_out, int out_size) {
    const float* x   = (const float*)d_in[0];
    const void*  ei  = d_in[1];
    const float* W1l = (const float*)d_in[2];
    const float* b1  = (const float*)d_in[3];
    const float* W1r = (const float*)d_in[4];
    const float* W2l = (const float*)d_in[5];
    const float* b2  = (const float*)d_in[6];
    const float* W2r = (const float*)d_in[7];
    float* out = (float*)d_out;

    const int N = in_sizes[0] / NFEAT;
    const int E = in_sizes[1] / 2;
    const int NB = (N + SCAN_CHUNK - 1) / SCAN_CHUNK;
    const int EH = ((E + 1) / 2 + 255) / 256;

    void *t1p, *t2p;
    cudaGetSymbolAddress(&t1p, g_t1h);
    cudaGetSymbolAddress(&t2p, g_t2h);

    cudaFuncSetAttribute(k_gemm1_wmma, cudaFuncAttributeMaxDynamicSharedMemorySize, GEMM1_SMEM);
    cudaFuncSetAttribute(k_gemm2_wmma, cudaFuncAttributeMaxDynamicSharedMemorySize, GEMM2_SMEM);

    int g1 = 296;                          // 2 CTA/SM persistent
    int nt1 = (N + 127) / 128;
    if (g1 > nt1) g1 = nt1;
    int g2 = 296;
    if (g2 > (N + 127) / 128) g2 = (N + 127) / 128;

    // fork: side stream = weights + GEMM1; main stream = graph build
    cudaEventRecord(g_evFork, 0);
    cudaStreamWaitEvent(g_s2, g_evFork, 0);

    k_wsplit_all<<<21, 256, 0, g_s2>>>(W1l, W1r, W2l, W2r);            // #1
    k_hist<<<EH, 256>>>(ei, E, N);                                     // #2
    k_scan<<<NB, 1024>>>(N);                                           // #3
    k_gemm1_wmma<<<g1, 256, GEMM1_SMEM, g_s2>>>(x, (__half*)t1p, N);   // #4
    k_fill<<<EH, 256>>>(ei, E, N);                                     // #5

    // join
    cudaEventRecord(g_evG1, g_s2);
    cudaStreamWaitEvent(0, g_evG1, 0);

    // tail
    int tot1 = N * 8;
    k_finish1<<<(tot1 + 255) / 256, 256>>>((const __half*)t1p, b1, N);           // #6
    k_gemm2_wmma<<<g2, 320, GEMM2_SMEM>>>((__half*)t2p, N);                      // #7
    int tot2 = N * 5;
    k_finish2<<<(tot2 + 255) / 256, 256>>>((const __half*)t2p, b2, out, N);      // #8
}